// round 13
// baseline (speedup 1.0000x reference)
#include <cuda_runtime.h>
#include <cuda_bf16.h>
#include <cuda_fp16.h>
#include <math.h>
#include <stdint.h>

#define B_  512
#define S_  512
#define DI_ 256
#define DO_ 256

// fp16 fragment-packed weights: [g(=t*8+chunk)][w(8)][s2(2)][mt(2)][lane(32)] float4 (=8 f16)
__device__ float4 WhP_h[(size_t)S_ * 8 * 8 * 128];   // 67 MB
__device__ float4 WxP_h[(size_t)S_ * 8 * 8 * 128];   // 67 MB
// fp16 x, tile-major: [(t*8 + btile)*64 + r][k=256] halfs  (134 MB)
__device__ __half xh_g[(size_t)S_ * B_ * DI_];

// ---------------- helpers ----------------

__device__ __forceinline__ void cpasync16(void* smem_dst, const void* gsrc) {
    unsigned saddr = (unsigned)__cvta_generic_to_shared(smem_dst);
    asm volatile("cp.async.cg.shared.global [%0], [%1], 16;\n" :: "r"(saddr), "l"(gsrc));
}
__device__ __forceinline__ void cp_commit() { asm volatile("cp.async.commit_group;\n"); }
template <int N> __device__ __forceinline__ void cp_wait() {
    asm volatile("cp.async.wait_group %0;\n" :: "n"(N));
}
__device__ __forceinline__ unsigned f2u(float f) { return __float_as_uint(f); }
__device__ __forceinline__ float fast_tanh(float x) {
    float e = __expf(2.0f * x);
    return 1.0f - __fdividef(2.0f, e + 1.0f);
}
__device__ __forceinline__ uint32_t smem_u32(const void* p) {
    return (uint32_t)__cvta_generic_to_shared(p);
}
__device__ __forceinline__ uint32_t packh2(float a, float b) {
    __half2 h = __floats2half2_rn(a, b);
    return *(uint32_t*)&h;
}

__device__ __forceinline__ void mma_f16(float c[4],
                                        unsigned a0, unsigned a1, unsigned a2, unsigned a3,
                                        unsigned b0, unsigned b1) {
    asm volatile(
        "mma.sync.aligned.m16n8k16.row.col.f32.f16.f16.f32 "
        "{%0,%1,%2,%3}, {%4,%5,%6,%7}, {%8,%9}, {%0,%1,%2,%3};\n"
        : "+f"(c[0]), "+f"(c[1]), "+f"(c[2]), "+f"(c[3])
        : "r"(a0), "r"(a1), "r"(a2), "r"(a3), "r"(b0), "r"(b1));
}

#define LDSM_X4(r0, r1, r2, r3, addr) \
    asm volatile("ldmatrix.sync.aligned.m8n8.x4.shared.b16 {%0,%1,%2,%3}, [%4];" \
                 : "=r"(r0), "=r"(r1), "=r"(r2), "=r"(r3) : "r"(addr))

// ---------------- Prepack A: W (Wh or Wx, both [t][k][m]) -> fp16 fragments ----------------
// grid (slab=8, t=512), 256 thr. Fragment element [w][s2][mt][lane]:
//   r=lane>>2, cc=(lane&3)*2, m0=w*32+mt*16+r, kk=s2*16+cc; A[m][k]=W[k][m].

__global__ __launch_bounds__(256, 1) void prepack_w(const float* __restrict__ W, int toWx)
{
    __shared__ float tile[32 * 260];
    const int slab = blockIdx.x;
    const int t    = blockIdx.y;
    const int tid  = threadIdx.x;
    float4* dst = toWx ? WxP_h : WhP_h;

    const float* src = W + (size_t)t * (DO_ * DO_) + (size_t)slab * 32 * DO_;
#pragma unroll
    for (int j = 0; j < 8; j++) {
        int idx = tid + j * 256;
        int r = idx >> 6, q = idx & 63;
        *(float4*)&tile[r * 260 + q * 4] = *(const float4*)&src[r * DO_ + q * 4];
    }
    __syncthreads();

    const size_t g = (size_t)t * 8 + slab;
#pragma unroll
    for (int j = 0; j < 4; j++) {
        int idx  = tid + j * 256;
        int lane = idx & 31;
        int mt   = (idx >> 5) & 1;
        int s2   = (idx >> 6) & 1;
        int wm   = (idx >> 7) & 7;
        int r    = lane >> 2, cc = (lane & 3) * 2;
        int m0   = wm * 32 + mt * 16 + r;
        int kk   = s2 * 16 + cc;
        float4 v;
        v.x = __uint_as_float(packh2(tile[kk * 260 + m0],       tile[(kk + 1) * 260 + m0]));
        v.y = __uint_as_float(packh2(tile[kk * 260 + m0 + 8],   tile[(kk + 1) * 260 + m0 + 8]));
        v.z = __uint_as_float(packh2(tile[(kk + 8) * 260 + m0], tile[(kk + 9) * 260 + m0]));
        v.w = __uint_as_float(packh2(tile[(kk + 8) * 260 + m0 + 8], tile[(kk + 9) * 260 + m0 + 8]));
        dst[(g * 8 + wm) * 128 + (s2 * 2 + mt) * 32 + lane] = v;
    }
}

// ---------------- Prepack x -> fp16 tile-major ----------------
// grid (btile=8, t=512), 256 thr. xh[((t*8+btile)*64 + r)*256 + k] = (half)x[btile*64+r][t][k].

__global__ __launch_bounds__(256, 1) void prepack_x(const float* __restrict__ x)
{
    const int btile = blockIdx.x;
    const int t     = blockIdx.y;
    const int tid   = threadIdx.x;
    const size_t obase = ((size_t)t * 8 + btile) * 64;

#pragma unroll
    for (int j = 0; j < 16; j++) {
        int idx = tid + j * 256;          // 0..4095
        int r = idx >> 6, q = idx & 63;   // row r, float4 q
        float4 v = *(const float4*)&x[((size_t)(btile * 64 + r) * S_ + t) * DI_ + q * 4];
        uint2 o;
        o.x = packh2(v.x, v.y);
        o.y = packh2(v.z, v.w);
        *(uint2*)&xh_g[(obase + r) * DI_ + q * 4] = o;
    }
}

// ---------------- Phase 1 v3 (fp16): Z = x @ Wx, fragment-streamed ----------------
// grid 4096: t = bid>>3, btile = bid&7. 256 thr, 8 warps; warp w owns M cols [w*32,+32).
// B: x tile 64x256 fp16 in smem (stride 264 halfs), ldmatrix.x4 per (ng, chunk).
// A: WxP_h fragments via LDG.128, 2-stage static ring. 32 mma per chunk, 8 chunks.

#define P1_XSTR 264

__global__ __launch_bounds__(256, 2) void rnn_phase1(float* __restrict__ out)
{
    __shared__ __align__(16) __half xs[64 * P1_XSTR];

    const int tid  = threadIdx.x;
    const int w    = tid >> 5, lane = tid & 31;
    const int grp  = lane >> 2, tig = lane & 3;
    const int t     = blockIdx.x >> 3;
    const int btile = blockIdx.x & 7;

    // load x tile (64 rows x 256 halfs) into smem
    {
        const __half* src = &xh_g[((size_t)t * 8 + btile) * 64 * DI_];
#pragma unroll
        for (int j = 0; j < 8; j++) {
            int i = tid + j * 256;
            int r = i >> 5, q = i & 31;       // row r, 16B unit q (8 halfs)
            cpasync16(&xs[r * P1_XSTR + q * 8], src + r * DI_ + q * 8);
        }
        cp_commit();
    }

    float4 A[2][2][2];   // [stage][s2][mt]
    auto ldA = [&](int c, int st) {
        const size_t base = (((size_t)t * 8 + c) * 8 + w) * 128 + lane;
        A[st][0][0] = __ldg(&WxP_h[base]);
        A[st][0][1] = __ldg(&WxP_h[base + 32]);
        A[st][1][0] = __ldg(&WxP_h[base + 64]);
        A[st][1][1] = __ldg(&WxP_h[base + 96]);
    };
    ldA(0, 0);
    ldA(1, 1);

    float acc[2][8][4];
#pragma unroll
    for (int mt = 0; mt < 2; mt++)
#pragma unroll
        for (int ng = 0; ng < 8; ng++)
#pragma unroll
            for (int i = 0; i < 4; i++) acc[mt][ng][i] = 0.f;

    cp_wait<0>();
    __syncthreads();

    const uint32_t xs_base = smem_u32(xs);
    const uint32_t lmb = xs_base + (uint32_t)(lane & 7) * (P1_XSTR * 2) + (uint32_t)(lane >> 3) * 16;

#pragma unroll
    for (int c = 0; c < 8; c++) {
#pragma unroll
        for (int ng = 0; ng < 8; ng++) {
            uint32_t b0, b1, b2, b3;
            LDSM_X4(b0, b1, b2, b3, lmb + (uint32_t)ng * (8 * P1_XSTR * 2) + (uint32_t)c * 64);
            {
                const float4 a0 = A[c & 1][0][0];
                mma_f16(acc[0][ng], f2u(a0.x), f2u(a0.y), f2u(a0.z), f2u(a0.w), b0, b1);
                const float4 a1 = A[c & 1][0][1];
                mma_f16(acc[1][ng], f2u(a1.x), f2u(a1.y), f2u(a1.z), f2u(a1.w), b0, b1);
            }
            {
                const float4 a0 = A[c & 1][1][0];
                mma_f16(acc[0][ng], f2u(a0.x), f2u(a0.y), f2u(a0.z), f2u(a0.w), b2, b3);
                const float4 a1 = A[c & 1][1][1];
                mma_f16(acc[1][ng], f2u(a1.x), f2u(a1.y), f2u(a1.z), f2u(a1.w), b2, b3);
            }
        }
        if (c + 2 < 8) ldA(c + 2, c & 1);
    }

    // epilogue: Z[b][t][col]
#pragma unroll
    for (int mt = 0; mt < 2; mt++) {
        const int col = w * 32 + mt * 16 + grp;
#pragma unroll
        for (int ng = 0; ng < 8; ng++) {
            const int b0 = btile * 64 + ng * 8 + 2 * tig;
            out[((size_t)b0       * S_ + t) * DO_ + col]     = acc[mt][ng][0];
            out[((size_t)(b0 + 1) * S_ + t) * DO_ + col]     = acc[mt][ng][1];
            out[((size_t)b0       * S_ + t) * DO_ + col + 8] = acc[mt][ng][2];
            out[((size_t)(b0 + 1) * S_ + t) * DO_ + col + 8] = acc[mt][ng][3];
        }
    }
}

// ---------------- Phase 2 (R10 verbatim — fp16, k-split, 64 CTAs x 512 thr) ----------------

#define P2_HSTR 264

__global__ __launch_bounds__(512, 1) void rnn_phase2(float* __restrict__ out)
{
    __shared__ __align__(16) __half hs2[8 * P2_HSTR];
    __shared__ __align__(16) float4 scr[2][8][32];

    const int tid  = threadIdx.x;
    const int w    = tid >> 5, lane = tid & 31;
    const int grp  = lane >> 2, tig = lane & 3;
    const int kh   = w >> 3, wm = w & 7;
    const int brow = blockIdx.x * 8;
    const int m0   = wm * 32 + kh * 16 + grp;
    const int n0   = 2 * tig;

    for (int i = tid; i < 8 * P2_HSTR / 2; i += 512) ((uint32_t*)hs2)[i] = 0u;
    __syncthreads();

    const uint32_t hs_base = smem_u32(hs2);
    const uint32_t lmb = hs_base + (uint32_t)(lane & 7) * (P2_HSTR * 2) + (uint32_t)(lane >> 3) * 16;

    float4 A[2][2][2];
    auto ldA = [&](int s, int st) {
        const int g = ((s >> 2) << 3) | (kh << 2) | (s & 3);
        const size_t base = ((size_t)g * 8 + wm) * 128 + lane;
        A[st][0][0] = __ldg(&WhP_h[base]);
        A[st][0][1] = __ldg(&WhP_h[base + 32]);
        A[st][1][0] = __ldg(&WhP_h[base + 64]);
        A[st][1][1] = __ldg(&WhP_h[base + 96]);
    };
    ldA(0, 0);
    ldA(1, 1);

    float acc[2][4];
    float z[4];
    int s = 0;

    for (int t = 0; t < S_; t++) {
#pragma unroll
        for (int mt = 0; mt < 2; mt++)
#pragma unroll
            for (int i = 0; i < 4; i++) acc[mt][i] = 0.f;

        z[0] = __ldg(&out[((size_t)(brow + n0)     * S_ + t) * DO_ + m0]);
        z[1] = __ldg(&out[((size_t)(brow + n0 + 1) * S_ + t) * DO_ + m0]);
        z[2] = __ldg(&out[((size_t)(brow + n0)     * S_ + t) * DO_ + m0 + 8]);
        z[3] = __ldg(&out[((size_t)(brow + n0 + 1) * S_ + t) * DO_ + m0 + 8]);

        for (int c = 0; c < 4; c++) {
            const int st = s & 1;
            const int k0 = kh * 128 + c * 32;
            uint32_t b0, b1, b2, b3;
            LDSM_X4(b0, b1, b2, b3, lmb + (uint32_t)k0 * 2);
            {
                const float4 af0 = A[st][0][0];
                mma_f16(acc[0], f2u(af0.x), f2u(af0.y), f2u(af0.z), f2u(af0.w), b0, b1);
                const float4 af1 = A[st][0][1];
                mma_f16(acc[1], f2u(af1.x), f2u(af1.y), f2u(af1.z), f2u(af1.w), b0, b1);
            }
            {
                const float4 af0 = A[st][1][0];
                mma_f16(acc[0], f2u(af0.x), f2u(af0.y), f2u(af0.z), f2u(af0.w), b2, b3);
                const float4 af1 = A[st][1][1];
                mma_f16(acc[1], f2u(af1.x), f2u(af1.y), f2u(af1.z), f2u(af1.w), b2, b3);
            }
            if (s + 2 < 4 * S_) ldA(s + 2, st);
            s++;
        }

        if (kh == 0) {
            scr[0][wm][lane] = make_float4(acc[1][0], acc[1][1], acc[1][2], acc[1][3]);
        } else {
            scr[1][wm][lane] = make_float4(acc[0][0], acc[0][1], acc[0][2], acc[0][3]);
        }
        __syncthreads();

        const float4 p = scr[kh ^ 1][wm][lane];
        const float h0 = fast_tanh(z[0] + acc[kh][0] + p.x);
        const float h1 = fast_tanh(z[1] + acc[kh][1] + p.y);
        const float h2 = fast_tanh(z[2] + acc[kh][2] + p.z);
        const float h3 = fast_tanh(z[3] + acc[kh][3] + p.w);

        out[((size_t)(brow + n0)     * S_ + t) * DO_ + m0]     = h0;
        out[((size_t)(brow + n0 + 1) * S_ + t) * DO_ + m0]     = h1;
        out[((size_t)(brow + n0)     * S_ + t) * DO_ + m0 + 8] = h2;
        out[((size_t)(brow + n0 + 1) * S_ + t) * DO_ + m0 + 8] = h3;

        hs2[n0 * P2_HSTR + m0]           = __float2half_rn(h0);
        hs2[(n0 + 1) * P2_HSTR + m0]     = __float2half_rn(h1);
        hs2[n0 * P2_HSTR + m0 + 8]       = __float2half_rn(h2);
        hs2[(n0 + 1) * P2_HSTR + m0 + 8] = __float2half_rn(h3);

        __syncthreads();
    }
}

// ---------------- launch ----------------

extern "C" void kernel_launch(void* const* d_in, const int* in_sizes, int n_in,
                              void* d_out, int out_size)
{
    const float* x  = (const float*)d_in[0];   // [B, S, DI]
    const float* Wx = (const float*)d_in[1];   // [S, DI, DO]
    const float* Wh = (const float*)d_in[2];   // [S, DO, DO]
    float* out = (float*)d_out;                // [B, S, DO]

    prepack_w<<<dim3(8, S_), 256>>>(Wh, 0);
    prepack_w<<<dim3(8, S_), 256>>>(Wx, 1);
    prepack_x<<<dim3(8, S_), 256>>>(x);

    rnn_phase1<<<S_ * 8, 256>>>(out);
    rnn_phase2<<<B_ / 8, 512>>>(out);
}

// round 14
// speedup vs baseline: 1.3407x; 1.3407x over previous
#include <cuda_runtime.h>
#include <cuda_bf16.h>
#include <cuda_fp16.h>
#include <math.h>
#include <stdint.h>

#define B_  512
#define S_  512
#define DI_ 256
#define DO_ 256

// fp16 fragment-packed weights: [g(=t*8+chunk)][w(8)][s2(2)][mt(2)][lane(32)] float4 (=8 f16)
__device__ float4 WhP_h[(size_t)S_ * 8 * 8 * 128];   // 67 MB
__device__ float4 WxP_h[(size_t)S_ * 8 * 8 * 128];   // 67 MB
// fp16 x, tile-major: [(t*8 + btile)*64 + r][k=256] halfs  (134 MB)
__device__ __half xh_g[(size_t)S_ * B_ * DI_];

// ---------------- helpers ----------------

__device__ __forceinline__ void cpasync16(void* smem_dst, const void* gsrc) {
    unsigned saddr = (unsigned)__cvta_generic_to_shared(smem_dst);
    asm volatile("cp.async.cg.shared.global [%0], [%1], 16;\n" :: "r"(saddr), "l"(gsrc));
}
__device__ __forceinline__ void cp_commit() { asm volatile("cp.async.commit_group;\n"); }
template <int N> __device__ __forceinline__ void cp_wait() {
    asm volatile("cp.async.wait_group %0;\n" :: "n"(N));
}
__device__ __forceinline__ unsigned f2u(float f) { return __float_as_uint(f); }
__device__ __forceinline__ float fast_tanh(float x) {
    float e = __expf(2.0f * x);
    return 1.0f - __fdividef(2.0f, e + 1.0f);
}
__device__ __forceinline__ uint32_t smem_u32(const void* p) {
    return (uint32_t)__cvta_generic_to_shared(p);
}
__device__ __forceinline__ uint32_t packh2(float a, float b) {
    __half2 h = __floats2half2_rn(a, b);
    return *(uint32_t*)&h;
}

__device__ __forceinline__ void mma_f16(float c[4],
                                        unsigned a0, unsigned a1, unsigned a2, unsigned a3,
                                        unsigned b0, unsigned b1) {
    asm volatile(
        "mma.sync.aligned.m16n8k16.row.col.f32.f16.f16.f32 "
        "{%0,%1,%2,%3}, {%4,%5,%6,%7}, {%8,%9}, {%0,%1,%2,%3};\n"
        : "+f"(c[0]), "+f"(c[1]), "+f"(c[2]), "+f"(c[3])
        : "r"(a0), "r"(a1), "r"(a2), "r"(a3), "r"(b0), "r"(b1));
}

#define LDSM_X4(r0, r1, r2, r3, addr) \
    asm volatile("ldmatrix.sync.aligned.m8n8.x4.shared.b16 {%0,%1,%2,%3}, [%4];" \
                 : "=r"(r0), "=r"(r1), "=r"(r2), "=r"(r3) : "r"(addr))

// ---------------- Prepack W (Wh or Wx) -> fp16 fragments (R13 verbatim) ----------------

__global__ __launch_bounds__(256, 1) void prepack_w(const float* __restrict__ W, int toWx)
{
    __shared__ float tile[32 * 260];
    const int slab = blockIdx.x;
    const int t    = blockIdx.y;
    const int tid  = threadIdx.x;
    float4* dst = toWx ? WxP_h : WhP_h;

    const float* src = W + (size_t)t * (DO_ * DO_) + (size_t)slab * 32 * DO_;
#pragma unroll
    for (int j = 0; j < 8; j++) {
        int idx = tid + j * 256;
        int r = idx >> 6, q = idx & 63;
        *(float4*)&tile[r * 260 + q * 4] = *(const float4*)&src[r * DO_ + q * 4];
    }
    __syncthreads();

    const size_t g = (size_t)t * 8 + slab;
#pragma unroll
    for (int j = 0; j < 4; j++) {
        int idx  = tid + j * 256;
        int lane = idx & 31;
        int mt   = (idx >> 5) & 1;
        int s2   = (idx >> 6) & 1;
        int wm   = (idx >> 7) & 7;
        int r    = lane >> 2, cc = (lane & 3) * 2;
        int m0   = wm * 32 + mt * 16 + r;
        int kk   = s2 * 16 + cc;
        float4 v;
        v.x = __uint_as_float(packh2(tile[kk * 260 + m0],       tile[(kk + 1) * 260 + m0]));
        v.y = __uint_as_float(packh2(tile[kk * 260 + m0 + 8],   tile[(kk + 1) * 260 + m0 + 8]));
        v.z = __uint_as_float(packh2(tile[(kk + 8) * 260 + m0], tile[(kk + 9) * 260 + m0]));
        v.w = __uint_as_float(packh2(tile[(kk + 8) * 260 + m0 + 8], tile[(kk + 9) * 260 + m0 + 8]));
        dst[(g * 8 + wm) * 128 + (s2 * 2 + mt) * 32 + lane] = v;
    }
}

// ---------------- Prepack x -> fp16 tile-major (R13 verbatim) ----------------

__global__ __launch_bounds__(256, 1) void prepack_x(const float* __restrict__ x)
{
    const int btile = blockIdx.x;
    const int t     = blockIdx.y;
    const int tid   = threadIdx.x;
    const size_t obase = ((size_t)t * 8 + btile) * 64;

#pragma unroll
    for (int j = 0; j < 16; j++) {
        int idx = tid + j * 256;
        int r = idx >> 6, q = idx & 63;
        float4 v = *(const float4*)&x[((size_t)(btile * 64 + r) * S_ + t) * DI_ + q * 4];
        uint2 o;
        o.x = packh2(v.x, v.y);
        o.y = packh2(v.z, v.w);
        *(uint2*)&xh_g[(obase + r) * DI_ + q * 4] = o;
    }
}

// ---------------- Phase 1 v4 (fp16): Z = x @ Wx, smem-staged coalesced epilogue ----------------
// grid 4096: t = bid>>3, btile = bid&7. 256 thr, 8 warps; warp w owns M cols [w*32,+32).
// Epilogue: scatter acc into smem Z-tile (conflict-free STS), then contiguous float4 STG.128.

#define P1_XSTR 264
#define P1_ZSTR 260
#define P1_SMEMB (64 * P1_ZSTR * 4)   // 66,560 B (also covers the 33,792 B x-tile)

__global__ __launch_bounds__(256, 2) void rnn_phase1(float* __restrict__ out)
{
    extern __shared__ float smf1[];
    __half* xs = (__half*)smf1;

    const int tid  = threadIdx.x;
    const int w    = tid >> 5, lane = tid & 31;
    const int grp  = lane >> 2, tig = lane & 3;
    const int t     = blockIdx.x >> 3;
    const int btile = blockIdx.x & 7;

    // load x tile (64 rows x 256 halfs) into smem
    {
        const __half* src = &xh_g[((size_t)t * 8 + btile) * 64 * DI_];
#pragma unroll
        for (int j = 0; j < 8; j++) {
            int i = tid + j * 256;
            int r = i >> 5, q = i & 31;
            cpasync16(&xs[r * P1_XSTR + q * 8], src + r * DI_ + q * 8);
        }
        cp_commit();
    }

    float4 A[2][2][2];   // [stage][s2][mt]
    auto ldA = [&](int c, int st) {
        const size_t base = (((size_t)t * 8 + c) * 8 + w) * 128 + lane;
        A[st][0][0] = __ldg(&WxP_h[base]);
        A[st][0][1] = __ldg(&WxP_h[base + 32]);
        A[st][1][0] = __ldg(&WxP_h[base + 64]);
        A[st][1][1] = __ldg(&WxP_h[base + 96]);
    };
    ldA(0, 0);
    ldA(1, 1);

    float acc[2][8][4];
#pragma unroll
    for (int mt = 0; mt < 2; mt++)
#pragma unroll
        for (int ng = 0; ng < 8; ng++)
#pragma unroll
            for (int i = 0; i < 4; i++) acc[mt][ng][i] = 0.f;

    cp_wait<0>();
    __syncthreads();

    const uint32_t xs_base = smem_u32(xs);
    const uint32_t lmb = xs_base + (uint32_t)(lane & 7) * (P1_XSTR * 2) + (uint32_t)(lane >> 3) * 16;

#pragma unroll
    for (int c = 0; c < 8; c++) {
#pragma unroll
        for (int ng = 0; ng < 8; ng++) {
            uint32_t b0, b1, b2, b3;
            LDSM_X4(b0, b1, b2, b3, lmb + (uint32_t)ng * (8 * P1_XSTR * 2) + (uint32_t)c * 64);
            {
                const float4 a0 = A[c & 1][0][0];
                mma_f16(acc[0][ng], f2u(a0.x), f2u(a0.y), f2u(a0.z), f2u(a0.w), b0, b1);
                const float4 a1 = A[c & 1][0][1];
                mma_f16(acc[1][ng], f2u(a1.x), f2u(a1.y), f2u(a1.z), f2u(a1.w), b0, b1);
            }
            {
                const float4 a0 = A[c & 1][1][0];
                mma_f16(acc[0][ng], f2u(a0.x), f2u(a0.y), f2u(a0.z), f2u(a0.w), b2, b3);
                const float4 a1 = A[c & 1][1][1];
                mma_f16(acc[1][ng], f2u(a1.x), f2u(a1.y), f2u(a1.z), f2u(a1.w), b2, b3);
            }
        }
        if (c + 2 < 8) ldA(c + 2, c & 1);
    }

    // ---- epilogue via smem: scatter STS (conflict-free), then coalesced STG.128 ----
    float* zs = smf1;          // aliases xs; safe after barrier below
    __syncthreads();           // all LDSM reads of xs complete

#pragma unroll
    for (int mt = 0; mt < 2; mt++) {
        const int col = w * 32 + mt * 16 + grp;
#pragma unroll
        for (int ng = 0; ng < 8; ng++) {
            const int r0 = ng * 8 + 2 * tig;
            zs[r0 * P1_ZSTR + col]           = acc[mt][ng][0];
            zs[(r0 + 1) * P1_ZSTR + col]     = acc[mt][ng][1];
            zs[r0 * P1_ZSTR + col + 8]       = acc[mt][ng][2];
            zs[(r0 + 1) * P1_ZSTR + col + 8] = acc[mt][ng][3];
        }
    }
    __syncthreads();

    const int rl = lane >> 4;         // 0/1
    const int c4 = (lane & 15) * 4;   // float4 col base
#pragma unroll
    for (int it = 0; it < 4; it++) {
        const int row = w * 8 + it * 2 + rl;
        const size_t ob = ((size_t)(btile * 64 + row) * S_ + t) * DO_;
#pragma unroll
        for (int q = 0; q < 4; q++) {
            float4 v = *(float4*)&zs[row * P1_ZSTR + q * 64 + c4];
            *(float4*)&out[ob + q * 64 + c4] = v;
        }
    }
}

// ---------------- Phase 2 (R10/R13 verbatim — fp16, k-split, 64 CTAs x 512 thr) ----------------

#define P2_HSTR 264

__global__ __launch_bounds__(512, 1) void rnn_phase2(float* __restrict__ out)
{
    __shared__ __align__(16) __half hs2[8 * P2_HSTR];
    __shared__ __align__(16) float4 scr[2][8][32];

    const int tid  = threadIdx.x;
    const int w    = tid >> 5, lane = tid & 31;
    const int grp  = lane >> 2, tig = lane & 3;
    const int kh   = w >> 3, wm = w & 7;
    const int brow = blockIdx.x * 8;
    const int m0   = wm * 32 + kh * 16 + grp;
    const int n0   = 2 * tig;

    for (int i = tid; i < 8 * P2_HSTR / 2; i += 512) ((uint32_t*)hs2)[i] = 0u;
    __syncthreads();

    const uint32_t hs_base = smem_u32(hs2);
    const uint32_t lmb = hs_base + (uint32_t)(lane & 7) * (P2_HSTR * 2) + (uint32_t)(lane >> 3) * 16;

    float4 A[2][2][2];
    auto ldA = [&](int s, int st) {
        const int g = ((s >> 2) << 3) | (kh << 2) | (s & 3);
        const size_t base = ((size_t)g * 8 + wm) * 128 + lane;
        A[st][0][0] = __ldg(&WhP_h[base]);
        A[st][0][1] = __ldg(&WhP_h[base + 32]);
        A[st][1][0] = __ldg(&WhP_h[base + 64]);
        A[st][1][1] = __ldg(&WhP_h[base + 96]);
    };
    ldA(0, 0);
    ldA(1, 1);

    float acc[2][4];
    float z[4];
    int s = 0;

    for (int t = 0; t < S_; t++) {
#pragma unroll
        for (int mt = 0; mt < 2; mt++)
#pragma unroll
            for (int i = 0; i < 4; i++) acc[mt][i] = 0.f;

        z[0] = __ldg(&out[((size_t)(brow + n0)     * S_ + t) * DO_ + m0]);
        z[1] = __ldg(&out[((size_t)(brow + n0 + 1) * S_ + t) * DO_ + m0]);
        z[2] = __ldg(&out[((size_t)(brow + n0)     * S_ + t) * DO_ + m0 + 8]);
        z[3] = __ldg(&out[((size_t)(brow + n0 + 1) * S_ + t) * DO_ + m0 + 8]);

        for (int c = 0; c < 4; c++) {
            const int st = s & 1;
            const int k0 = kh * 128 + c * 32;
            uint32_t b0, b1, b2, b3;
            LDSM_X4(b0, b1, b2, b3, lmb + (uint32_t)k0 * 2);
            {
                const float4 af0 = A[st][0][0];
                mma_f16(acc[0], f2u(af0.x), f2u(af0.y), f2u(af0.z), f2u(af0.w), b0, b1);
                const float4 af1 = A[st][0][1];
                mma_f16(acc[1], f2u(af1.x), f2u(af1.y), f2u(af1.z), f2u(af1.w), b0, b1);
            }
            {
                const float4 af0 = A[st][1][0];
                mma_f16(acc[0], f2u(af0.x), f2u(af0.y), f2u(af0.z), f2u(af0.w), b2, b3);
                const float4 af1 = A[st][1][1];
                mma_f16(acc[1], f2u(af1.x), f2u(af1.y), f2u(af1.z), f2u(af1.w), b2, b3);
            }
            if (s + 2 < 4 * S_) ldA(s + 2, st);
            s++;
        }

        if (kh == 0) {
            scr[0][wm][lane] = make_float4(acc[1][0], acc[1][1], acc[1][2], acc[1][3]);
        } else {
            scr[1][wm][lane] = make_float4(acc[0][0], acc[0][1], acc[0][2], acc[0][3]);
        }
        __syncthreads();

        const float4 p = scr[kh ^ 1][wm][lane];
        const float h0 = fast_tanh(z[0] + acc[kh][0] + p.x);
        const float h1 = fast_tanh(z[1] + acc[kh][1] + p.y);
        const float h2 = fast_tanh(z[2] + acc[kh][2] + p.z);
        const float h3 = fast_tanh(z[3] + acc[kh][3] + p.w);

        out[((size_t)(brow + n0)     * S_ + t) * DO_ + m0]     = h0;
        out[((size_t)(brow + n0 + 1) * S_ + t) * DO_ + m0]     = h1;
        out[((size_t)(brow + n0)     * S_ + t) * DO_ + m0 + 8] = h2;
        out[((size_t)(brow + n0 + 1) * S_ + t) * DO_ + m0 + 8] = h3;

        hs2[n0 * P2_HSTR + m0]           = __float2half_rn(h0);
        hs2[(n0 + 1) * P2_HSTR + m0]     = __float2half_rn(h1);
        hs2[n0 * P2_HSTR + m0 + 8]       = __float2half_rn(h2);
        hs2[(n0 + 1) * P2_HSTR + m0 + 8] = __float2half_rn(h3);

        __syncthreads();
    }
}

// ---------------- launch ----------------

extern "C" void kernel_launch(void* const* d_in, const int* in_sizes, int n_in,
                              void* d_out, int out_size)
{
    const float* x  = (const float*)d_in[0];   // [B, S, DI]
    const float* Wx = (const float*)d_in[1];   // [S, DI, DO]
    const float* Wh = (const float*)d_in[2];   // [S, DO, DO]
    float* out = (float*)d_out;                // [B, S, DO]

    cudaFuncSetAttribute(rnn_phase1, cudaFuncAttributeMaxDynamicSharedMemorySize, P1_SMEMB);

    prepack_w<<<dim3(8, S_), 256>>>(Wh, 0);
    prepack_w<<<dim3(8, S_), 256>>>(Wx, 1);
    prepack_x<<<dim3(8, S_), 256>>>(x);

    rnn_phase1<<<S_ * 8, 256, P1_SMEMB>>>(out);
    rnn_phase2<<<B_ / 8, 512>>>(out);
}

// round 15
// speedup vs baseline: 1.4815x; 1.1051x over previous
#include <cuda_runtime.h>
#include <cuda_bf16.h>
#include <cuda_fp16.h>
#include <math.h>
#include <stdint.h>

#define B_  512
#define S_  512
#define DI_ 256
#define DO_ 256

// fp16 fragment-packed weights: [g(=t*8+chunk)][w(8)][s2(2)][mt(2)][lane(32)] float4 (=8 f16)
__device__ float4 WhP_h[(size_t)S_ * 8 * 8 * 128];   // 67 MB
__device__ float4 WxP_h[(size_t)S_ * 8 * 8 * 128];   // 67 MB

// ---------------- helpers ----------------

__device__ __forceinline__ unsigned f2u(float f) { return __float_as_uint(f); }
__device__ __forceinline__ float fast_tanh(float x) {
    float e = __expf(2.0f * x);
    return 1.0f - __fdividef(2.0f, e + 1.0f);
}
__device__ __forceinline__ uint32_t smem_u32(const void* p) {
    return (uint32_t)__cvta_generic_to_shared(p);
}
__device__ __forceinline__ uint32_t packh2(float a, float b) {
    __half2 h = __floats2half2_rn(a, b);
    return *(uint32_t*)&h;
}

__device__ __forceinline__ void mma_f16(float c[4],
                                        unsigned a0, unsigned a1, unsigned a2, unsigned a3,
                                        unsigned b0, unsigned b1) {
    asm volatile(
        "mma.sync.aligned.m16n8k16.row.col.f32.f16.f16.f32 "
        "{%0,%1,%2,%3}, {%4,%5,%6,%7}, {%8,%9}, {%0,%1,%2,%3};\n"
        : "+f"(c[0]), "+f"(c[1]), "+f"(c[2]), "+f"(c[3])
        : "r"(a0), "r"(a1), "r"(a2), "r"(a3), "r"(b0), "r"(b1));
}

#define LDSM_X4(r0, r1, r2, r3, addr) \
    asm volatile("ldmatrix.sync.aligned.m8n8.x4.shared.b16 {%0,%1,%2,%3}, [%4];" \
                 : "=r"(r0), "=r"(r1), "=r"(r2), "=r"(r3) : "r"(addr))

#define NBAR64(id) asm volatile("bar.sync %0, 64;" :: "r"(id) : "memory")

// ---------------- Prepack W (both weights, grid.z selects) -> fp16 fragments ----------------

__global__ __launch_bounds__(256, 1) void prepack_w(const float* __restrict__ Wh,
                                                    const float* __restrict__ Wx)
{
    __shared__ float tile[32 * 260];
    const int slab = blockIdx.x;
    const int t    = blockIdx.y;
    const int tid  = threadIdx.x;
    const float* W = blockIdx.z ? Wx : Wh;
    float4* dst    = blockIdx.z ? WxP_h : WhP_h;

    const float* src = W + (size_t)t * (DO_ * DO_) + (size_t)slab * 32 * DO_;
#pragma unroll
    for (int j = 0; j < 8; j++) {
        int idx = tid + j * 256;
        int r = idx >> 6, q = idx & 63;
        *(float4*)&tile[r * 260 + q * 4] = *(const float4*)&src[r * DO_ + q * 4];
    }
    __syncthreads();

    const size_t g = (size_t)t * 8 + slab;
#pragma unroll
    for (int j = 0; j < 4; j++) {
        int idx  = tid + j * 256;
        int lane = idx & 31;
        int mt   = (idx >> 5) & 1;
        int s2   = (idx >> 6) & 1;
        int wm   = (idx >> 7) & 7;
        int r    = lane >> 2, cc = (lane & 3) * 2;
        int m0   = wm * 32 + mt * 16 + r;
        int kk   = s2 * 16 + cc;
        float4 v;
        v.x = __uint_as_float(packh2(tile[kk * 260 + m0],       tile[(kk + 1) * 260 + m0]));
        v.y = __uint_as_float(packh2(tile[kk * 260 + m0 + 8],   tile[(kk + 1) * 260 + m0 + 8]));
        v.z = __uint_as_float(packh2(tile[(kk + 8) * 260 + m0], tile[(kk + 9) * 260 + m0]));
        v.w = __uint_as_float(packh2(tile[(kk + 8) * 260 + m0 + 8], tile[(kk + 9) * 260 + m0 + 8]));
        dst[(g * 8 + wm) * 128 + (s2 * 2 + mt) * 32 + lane] = v;
    }
}

// ---------------- Phase 1 v5 (fp16): Z = x @ Wx; in-kernel f32->fp16 x conversion ----------------
// grid 4096: t = bid>>3, btile = bid&7. 256 thr, 8 warps; warp w owns M cols [w*32,+32).
// x tile loaded as f32 from input, converted to fp16 in registers, STS'd (no prepack_x pass).
// Epilogue staged through smem for coalesced STG.128 (R14-proven).

#define P1_XSTR 264
#define P1_ZSTR 260
#define P1_SMEMB (64 * P1_ZSTR * 4)   // 66,560 B (covers the 33,792 B x-tile too)

__global__ __launch_bounds__(256, 2) void rnn_phase1(
    const float* __restrict__ x, float* __restrict__ out)
{
    extern __shared__ float smf1[];
    __half* xs = (__half*)smf1;

    const int tid  = threadIdx.x;
    const int w    = tid >> 5, lane = tid & 31;
    const int grp  = lane >> 2, tig = lane & 3;
    const int t     = blockIdx.x >> 3;
    const int btile = blockIdx.x & 7;

    // A-frag prefetches issued first to overlap with the x-tile conversion
    float4 A[2][2][2];   // [stage][s2][mt]
    auto ldA = [&](int c, int st) {
        const size_t base = (((size_t)t * 8 + c) * 8 + w) * 128 + lane;
        A[st][0][0] = __ldg(&WxP_h[base]);
        A[st][0][1] = __ldg(&WxP_h[base + 32]);
        A[st][1][0] = __ldg(&WxP_h[base + 64]);
        A[st][1][1] = __ldg(&WxP_h[base + 96]);
    };
    ldA(0, 0);
    ldA(1, 1);

    // load x tile (64 rows x 256 f32), convert to fp16, STS
    {
#pragma unroll
        for (int j = 0; j < 16; j++) {
            int i = tid + j * 256;            // 0..4095
            int r = i >> 6, q = i & 63;       // row r, float4 q
            float4 v = __ldg((const float4*)&x[((size_t)(btile * 64 + r) * S_ + t) * DI_ + q * 4]);
            uint2 o;
            o.x = packh2(v.x, v.y);
            o.y = packh2(v.z, v.w);
            *(uint2*)&xs[r * P1_XSTR + q * 4] = o;
        }
    }

    float acc[2][8][4];
#pragma unroll
    for (int mt = 0; mt < 2; mt++)
#pragma unroll
        for (int ng = 0; ng < 8; ng++)
#pragma unroll
            for (int i = 0; i < 4; i++) acc[mt][ng][i] = 0.f;

    __syncthreads();

    const uint32_t xs_base = smem_u32(xs);
    const uint32_t lmb = xs_base + (uint32_t)(lane & 7) * (P1_XSTR * 2) + (uint32_t)(lane >> 3) * 16;

#pragma unroll
    for (int c = 0; c < 8; c++) {
#pragma unroll
        for (int ng = 0; ng < 8; ng++) {
            uint32_t b0, b1, b2, b3;
            LDSM_X4(b0, b1, b2, b3, lmb + (uint32_t)ng * (8 * P1_XSTR * 2) + (uint32_t)c * 64);
            {
                const float4 a0 = A[c & 1][0][0];
                mma_f16(acc[0][ng], f2u(a0.x), f2u(a0.y), f2u(a0.z), f2u(a0.w), b0, b1);
                const float4 a1 = A[c & 1][0][1];
                mma_f16(acc[1][ng], f2u(a1.x), f2u(a1.y), f2u(a1.z), f2u(a1.w), b0, b1);
            }
            {
                const float4 a0 = A[c & 1][1][0];
                mma_f16(acc[0][ng], f2u(a0.x), f2u(a0.y), f2u(a0.z), f2u(a0.w), b2, b3);
                const float4 a1 = A[c & 1][1][1];
                mma_f16(acc[1][ng], f2u(a1.x), f2u(a1.y), f2u(a1.z), f2u(a1.w), b2, b3);
            }
        }
        if (c + 2 < 8) ldA(c + 2, c & 1);
    }

    // ---- epilogue via smem: scatter STS, then coalesced STG.128 ----
    float* zs = smf1;          // aliases xs; safe after barrier
    __syncthreads();

#pragma unroll
    for (int mt = 0; mt < 2; mt++) {
        const int col = w * 32 + mt * 16 + grp;
#pragma unroll
        for (int ng = 0; ng < 8; ng++) {
            const int r0 = ng * 8 + 2 * tig;
            zs[r0 * P1_ZSTR + col]           = acc[mt][ng][0];
            zs[(r0 + 1) * P1_ZSTR + col]     = acc[mt][ng][1];
            zs[r0 * P1_ZSTR + col + 8]       = acc[mt][ng][2];
            zs[(r0 + 1) * P1_ZSTR + col + 8] = acc[mt][ng][3];
        }
    }
    __syncthreads();

    const int rl = lane >> 4;
    const int c4 = (lane & 15) * 4;
#pragma unroll
    for (int it = 0; it < 4; it++) {
        const int row = w * 8 + it * 2 + rl;
        const size_t ob = ((size_t)(btile * 64 + row) * S_ + t) * DO_;
#pragma unroll
        for (int q = 0; q < 4; q++) {
            float4 v = *(float4*)&zs[row * P1_ZSTR + q * 64 + c4];
            *(float4*)&out[ob + q * 64 + c4] = v;
        }
    }
}

// ---------------- Phase 2: fp16 k-split, pairwise named-barrier exchange ----------------

#define P2_HSTR 264

__global__ __launch_bounds__(512, 1) void rnn_phase2(float* __restrict__ out)
{
    __shared__ __align__(16) __half hs2[8 * P2_HSTR];
    __shared__ __align__(16) float4 scr[2][8][32];

    const int tid  = threadIdx.x;
    const int w    = tid >> 5, lane = tid & 31;
    const int grp  = lane >> 2, tig = lane & 3;
    const int kh   = w >> 3, wm = w & 7;
    const int brow = blockIdx.x * 8;
    const int m0   = wm * 32 + kh * 16 + grp;
    const int n0   = 2 * tig;

    for (int i = tid; i < 8 * P2_HSTR / 2; i += 512) ((uint32_t*)hs2)[i] = 0u;
    __syncthreads();

    const uint32_t hs_base = smem_u32(hs2);
    const uint32_t lmb = hs_base + (uint32_t)(lane & 7) * (P2_HSTR * 2) + (uint32_t)(lane >> 3) * 16;

    float4 A[2][2][2];
    auto ldA = [&](int s, int st) {
        const int g = ((s >> 2) << 3) | (kh << 2) | (s & 3);
        const size_t base = ((size_t)g * 8 + wm) * 128 + lane;
        A[st][0][0] = __ldg(&WhP_h[base]);
        A[st][0][1] = __ldg(&WhP_h[base + 32]);
        A[st][1][0] = __ldg(&WhP_h[base + 64]);
        A[st][1][1] = __ldg(&WhP_h[base + 96]);
    };
    ldA(0, 0);
    ldA(1, 1);

    float acc[2][4];
    float z[4];
    int s = 0;

    for (int t = 0; t < S_; t++) {
#pragma unroll
        for (int mt = 0; mt < 2; mt++)
#pragma unroll
            for (int i = 0; i < 4; i++) acc[mt][i] = 0.f;

        z[0] = __ldg(&out[((size_t)(brow + n0)     * S_ + t) * DO_ + m0]);
        z[1] = __ldg(&out[((size_t)(brow + n0 + 1) * S_ + t) * DO_ + m0]);
        z[2] = __ldg(&out[((size_t)(brow + n0)     * S_ + t) * DO_ + m0 + 8]);
        z[3] = __ldg(&out[((size_t)(brow + n0 + 1) * S_ + t) * DO_ + m0 + 8]);

        for (int c = 0; c < 4; c++) {
            const int st = s & 1;
            const int k0 = kh * 128 + c * 32;
            uint32_t b0, b1, b2, b3;
            LDSM_X4(b0, b1, b2, b3, lmb + (uint32_t)k0 * 2);
            {
                const float4 af0 = A[st][0][0];
                mma_f16(acc[0], f2u(af0.x), f2u(af0.y), f2u(af0.z), f2u(af0.w), b0, b1);
                const float4 af1 = A[st][0][1];
                mma_f16(acc[1], f2u(af1.x), f2u(af1.y), f2u(af1.z), f2u(af1.w), b0, b1);
            }
            {
                const float4 af0 = A[st][1][0];
                mma_f16(acc[0], f2u(af0.x), f2u(af0.y), f2u(af0.z), f2u(af0.w), b2, b3);
                const float4 af1 = A[st][1][1];
                mma_f16(acc[1], f2u(af1.x), f2u(af1.y), f2u(af1.z), f2u(af1.w), b2, b3);
            }
            if (s + 2 < 4 * S_) ldA(s + 2, st);
            s++;
        }

        // pairwise exchange: only warps (wm, wm+8) need to sync here
        if (kh == 0) {
            scr[0][wm][lane] = make_float4(acc[1][0], acc[1][1], acc[1][2], acc[1][3]);
        } else {
            scr[1][wm][lane] = make_float4(acc[0][0], acc[0][1], acc[0][2], acc[0][3]);
        }
        NBAR64(wm + 1);

        const float4 p = scr[kh ^ 1][wm][lane];
        const float h0 = fast_tanh(z[0] + acc[kh][0] + p.x);
        const float h1 = fast_tanh(z[1] + acc[kh][1] + p.y);
        const float h2 = fast_tanh(z[2] + acc[kh][2] + p.z);
        const float h3 = fast_tanh(z[3] + acc[kh][3] + p.w);

        out[((size_t)(brow + n0)     * S_ + t) * DO_ + m0]     = h0;
        out[((size_t)(brow + n0 + 1) * S_ + t) * DO_ + m0]     = h1;
        out[((size_t)(brow + n0)     * S_ + t) * DO_ + m0 + 8] = h2;
        out[((size_t)(brow + n0 + 1) * S_ + t) * DO_ + m0 + 8] = h3;

        hs2[n0 * P2_HSTR + m0]           = __float2half_rn(h0);
        hs2[(n0 + 1) * P2_HSTR + m0]     = __float2half_rn(h1);
        hs2[n0 * P2_HSTR + m0 + 8]       = __float2half_rn(h2);
        hs2[(n0 + 1) * P2_HSTR + m0 + 8] = __float2half_rn(h3);

        __syncthreads();   // h_t fully visible before next step's LDSM (all-to-all)
    }
}

// ---------------- launch ----------------

extern "C" void kernel_launch(void* const* d_in, const int* in_sizes, int n_in,
                              void* d_out, int out_size)
{
    const float* x  = (const float*)d_in[0];   // [B, S, DI]
    const float* Wx = (const float*)d_in[1];   // [S, DI, DO]
    const float* Wh = (const float*)d_in[2];   // [S, DO, DO]
    float* out = (float*)d_out;                // [B, S, DO]

    cudaFuncSetAttribute(rnn_phase1, cudaFuncAttributeMaxDynamicSharedMemorySize, P1_SMEMB);

    prepack_w<<<dim3(8, S_, 2), 256>>>(Wh, Wx);
    rnn_phase1<<<S_ * 8, 256, P1_SMEMB>>>(x, out);
    rnn_phase2<<<B_ / 8, 512>>>(out);
}